// round 1
// baseline (speedup 1.0000x reference)
#include <cuda_runtime.h>

#define NN 100000
#define NE 1200000
#define NFEAT 64
#define NHID 256
#define NCLS 40

struct __align__(8) EdgeCW { int c; float w; };

__device__ int    g_is64;
__device__ int    g_deg[NN];
__device__ float  g_dinv[NN];
__device__ int    g_rowptr[NN + 1];
__device__ int    g_cursor[NN];
__device__ EdgeCW g_edges[NE];
__device__ float  g_h0[(size_t)NN * NFEAT];
__device__ float  g_h1[(size_t)NN * NFEAT];
__device__ float  g_y [(size_t)NN * NFEAT];

// ---------------------------------------------------------------------------
// Detect whether edge_index is int64 (high words of small nonneg values == 0)
// or int32 (random values, essentially never 64 zeros in a row).
// ---------------------------------------------------------------------------
__global__ void detect_kernel(const int* __restrict__ e32) {
    if (threadIdx.x == 0) {
        int allz = 1;
        for (int i = 0; i < 64; i++)
            if (e32[2 * i + 1] != 0) { allz = 0; break; }
        g_is64 = allz;
    }
}

__global__ void deg_init_kernel() {
    int i = blockIdx.x * blockDim.x + threadIdx.x;
    if (i < NN) g_deg[i] = 1;  // self loop
}

__global__ void deg_count_kernel(const void* __restrict__ eptr) {
    int e = blockIdx.x * blockDim.x + threadIdx.x;
    if (e >= NE) return;
    int r;
    if (g_is64) r = (int)((const long long*)eptr)[e];
    else        r = ((const int*)eptr)[e];
    atomicAdd(&g_deg[r], 1);
}

__global__ void dinv_kernel() {
    int i = blockIdx.x * blockDim.x + threadIdx.x;
    if (i < NN) g_dinv[i] = rsqrtf((float)g_deg[i]);
}

// Single-block exclusive scan of edge counts (deg-1) -> rowptr / cursor.
__global__ void scan_kernel() {
    __shared__ int part[1024];
    int t = threadIdx.x;
    const int CH = (NN + 1023) / 1024;  // 98
    int base = t * CH;
    int s = 0;
    for (int i = 0; i < CH; i++) {
        int idx = base + i;
        if (idx < NN) s += g_deg[idx] - 1;
    }
    part[t] = s;
    __syncthreads();
    for (int off = 1; off < 1024; off <<= 1) {
        int v = 0;
        if (t >= off) v = part[t - off];
        __syncthreads();
        if (t >= off) part[t] += v;
        __syncthreads();
    }
    int run = (t == 0) ? 0 : part[t - 1];
    for (int i = 0; i < CH; i++) {
        int idx = base + i;
        if (idx < NN) {
            g_rowptr[idx] = run;
            g_cursor[idx] = run;
            run += g_deg[idx] - 1;
        }
    }
    if (t == 1023) g_rowptr[NN] = part[1023];
}

__global__ void fill_kernel(const void* __restrict__ eptr) {
    int e = blockIdx.x * blockDim.x + threadIdx.x;
    if (e >= NE) return;
    int r, c;
    if (g_is64) {
        const long long* q = (const long long*)eptr;
        r = (int)q[e]; c = (int)q[e + NE];
    } else {
        const int* q = (const int*)eptr;
        r = q[e]; c = q[e + NE];
    }
    int pos = atomicAdd(&g_cursor[r], 1);
    EdgeCW ec;
    ec.c = c;
    ec.w = g_dinv[r] * g_dinv[c];
    g_edges[pos] = ec;
}

// h0 = x*0.5 ; y = x*0.5
__global__ void init_h_kernel(const float* __restrict__ x) {
    int i = blockIdx.x * blockDim.x + threadIdx.x;  // float4 index
    if (i >= NN * (NFEAT / 4)) return;
    float4 v = ((const float4*)x)[i];
    v.x *= 0.5f; v.y *= 0.5f; v.z *= 0.5f; v.w *= 0.5f;
    ((float4*)g_h0)[i] = v;
    ((float4*)g_y)[i]  = v;
}

// One warp per row: dst[r] = dinv[r]^2*src[r] + sum_j ew*src[col]; y[r] += dst[r]
__global__ void __launch_bounds__(256) spmm_kernel(int sel) {
    const float2* __restrict__ src = (const float2*)(sel ? g_h1 : g_h0);
    float2*       __restrict__ dst = (float2*)(sel ? g_h0 : g_h1);
    int gw = (blockIdx.x * blockDim.x + threadIdx.x) >> 5;
    if (gw >= NN) return;
    int lane = threadIdx.x & 31;

    int beg = g_rowptr[gw];
    int end = g_rowptr[gw + 1];
    float di = g_dinv[gw];
    float sw = di * di;

    float2 sv = src[gw * 32 + lane];
    float2 acc;
    acc.x = sw * sv.x;
    acc.y = sw * sv.y;

    for (int j = beg; j < end; j++) {
        EdgeCW e = g_edges[j];
        float2 hv = src[e.c * 32 + lane];
        acc.x = fmaf(e.w, hv.x, acc.x);
        acc.y = fmaf(e.w, hv.y, acc.y);
    }

    dst[gw * 32 + lane] = acc;
    float2* y2 = (float2*)g_y;
    float2 yv = y2[gw * 32 + lane];
    yv.x += acc.x;
    yv.y += acc.y;
    y2[gw * 32 + lane] = yv;
}

// ---------------------------------------------------------------------------
// Fused MLP: out = relu((y/9) @ W1 + b1) @ W2 + b2
// 64 rows per block; everything staged in dynamic smem.
// smem layout (floats): W1[64*256] | W2[256*40] | Y[64*65] | H[64*264]
// ---------------------------------------------------------------------------
#define MLP_SMEM_FLOATS (64 * 256 + 256 * 40 + 64 * 65 + 64 * 264)

__global__ void __launch_bounds__(256) mlp_kernel(
    const float* __restrict__ W1g, const float* __restrict__ b1g,
    const float* __restrict__ W2g, const float* __restrict__ b2g,
    float* __restrict__ out)
{
    extern __shared__ float sm[];
    float* sW1 = sm;                     // [f][c]  64 x 256 (scaled by 1/9)
    float* sW2 = sW1 + 64 * 256;         // [k][c]  256 x 40
    float* sY  = sW2 + 256 * 40;         // [r][f]  64 x 65 (pad)
    float* sH  = sY  + 64 * 65;          // [r][k]  64 x 264 (pad)

    int t = threadIdx.x;
    int row0 = blockIdx.x * 64;

    // Stage tiles
    for (int i = t; i < 64 * 64; i += 256) {
        int r = i >> 6, f = i & 63;
        float v = (row0 + r < NN) ? g_y[(size_t)(row0 + r) * 64 + f] : 0.f;
        sY[r * 65 + f] = v;
    }
    const float inv9 = 1.0f / 9.0f;
    for (int i = t; i < 64 * 256; i += 256) sW1[i] = W1g[i] * inv9;
    for (int i = t; i < 256 * 40; i += 256) sW2[i] = W2g[i];
    __syncthreads();

    // Phase 1: hid[64][256] = relu(Y @ W1 + b1)
    {
        int rg = t & 7;        // 8 row groups of 8
        int cg = t >> 3;       // 32 col groups of 8
        float acc[8][8];
        #pragma unroll
        for (int i = 0; i < 8; i++)
            #pragma unroll
            for (int j = 0; j < 8; j++) acc[i][j] = 0.f;

        #pragma unroll 4
        for (int f = 0; f < 64; f++) {
            float a[8];
            #pragma unroll
            for (int i = 0; i < 8; i++) a[i] = sY[(8 * rg + i) * 65 + f];
            float4 w0 = *(const float4*)&sW1[f * 256 + 8 * cg];
            float4 w1 = *(const float4*)&sW1[f * 256 + 8 * cg + 4];
            float w[8] = {w0.x, w0.y, w0.z, w0.w, w1.x, w1.y, w1.z, w1.w};
            #pragma unroll
            for (int i = 0; i < 8; i++)
                #pragma unroll
                for (int j = 0; j < 8; j++)
                    acc[i][j] = fmaf(a[i], w[j], acc[i][j]);
        }

        float bv[8];
        #pragma unroll
        for (int j = 0; j < 8; j++) bv[j] = __ldg(&b1g[8 * cg + j]);
        #pragma unroll
        for (int i = 0; i < 8; i++)
            #pragma unroll
            for (int j = 0; j < 8; j++)
                sH[(8 * rg + i) * 264 + 8 * cg + j] = fmaxf(acc[i][j] + bv[j], 0.f);
    }
    __syncthreads();

    // Phase 2: out[64][40] = hid @ W2 + b2
    {
        int r  = t >> 2;       // 64 rows
        int cq = t & 3;        // 4 col groups of 10
        int c0 = cq * 10;
        float acc2[10];
        #pragma unroll
        for (int j = 0; j < 10; j++) acc2[j] = __ldg(&b2g[c0 + j]);

        #pragma unroll 2
        for (int k = 0; k < 256; k++) {
            float hv = sH[r * 264 + k];
            #pragma unroll
            for (int j2 = 0; j2 < 5; j2++) {
                float2 w = *(const float2*)&sW2[k * 40 + c0 + 2 * j2];
                acc2[2 * j2]     = fmaf(hv, w.x, acc2[2 * j2]);
                acc2[2 * j2 + 1] = fmaf(hv, w.y, acc2[2 * j2 + 1]);
            }
        }
        if (row0 + r < NN) {
            #pragma unroll
            for (int j = 0; j < 10; j++)
                out[(size_t)(row0 + r) * 40 + c0 + j] = acc2[j];
        }
    }
}

extern "C" void kernel_launch(void* const* d_in, const int* in_sizes, int n_in,
                              void* d_out, int out_size) {
    const float* x   = (const float*)d_in[0];
    const void*  eix = d_in[1];
    const float* W1  = (const float*)d_in[2];
    const float* b1  = (const float*)d_in[3];
    const float* W2  = (const float*)d_in[4];
    const float* b2  = (const float*)d_in[5];
    float* out = (float*)d_out;

    cudaFuncSetAttribute(mlp_kernel, cudaFuncAttributeMaxDynamicSharedMemorySize,
                         MLP_SMEM_FLOATS * (int)sizeof(float));

    detect_kernel<<<1, 32>>>((const int*)eix);
    deg_init_kernel<<<(NN + 255) / 256, 256>>>();
    deg_count_kernel<<<(NE + 255) / 256, 256>>>(eix);
    dinv_kernel<<<(NN + 255) / 256, 256>>>();
    scan_kernel<<<1, 1024>>>();
    fill_kernel<<<(NE + 255) / 256, 256>>>(eix);
    init_h_kernel<<<(NN * (NFEAT / 4) + 255) / 256, 256>>>(x);

    int spmm_blocks = (NN * 32 + 255) / 256;  // one warp per row
    for (int it = 0; it < 8; it++)
        spmm_kernel<<<spmm_blocks, 256>>>(it & 1);

    int mlp_blocks = (NN + 63) / 64;
    mlp_kernel<<<mlp_blocks, 256, MLP_SMEM_FLOATS * (int)sizeof(float)>>>(
        W1, b1, W2, b2, out);
}

// round 2
// speedup vs baseline: 1.0104x; 1.0104x over previous
#include <cuda_runtime.h>
#include <cuda_fp16.h>

#define NN 100000
#define NE 1200000
#define NFEAT 64
#define NHID 256
#define NCLS 40

struct __align__(8) EdgeCW { int c; float w; };

__device__ int    g_is64;
__device__ int    g_deg[NN];
__device__ float  g_dinv[NN];
__device__ int    g_rowptr[NN + 1];
__device__ int    g_cursor[NN];
__device__ EdgeCW g_edges[NE];
__device__ __half g_h0[(size_t)NN * NFEAT];
__device__ __half g_h1[(size_t)NN * NFEAT];
__device__ float  g_y [(size_t)NN * NFEAT];

// ---------------------------------------------------------------------------
// Launch 1: detect int64-vs-int32 edge dtype + init degrees (self loop = 1)
// ---------------------------------------------------------------------------
__global__ void setup1_kernel(const int* __restrict__ e32) {
    int i = blockIdx.x * blockDim.x + threadIdx.x;
    if (i == 0) {
        int allz = 1;
        for (int k = 0; k < 64; k++)
            if (e32[2 * k + 1] != 0) { allz = 0; break; }
        g_is64 = allz;
    }
    if (i < NN) g_deg[i] = 1;
}

// Launch 2: degree histogram
__global__ void deg_count_kernel(const void* __restrict__ eptr) {
    int e = blockIdx.x * blockDim.x + threadIdx.x;
    if (e >= NE) return;
    int r;
    if (g_is64) r = (int)((const long long*)eptr)[e];
    else        r = ((const int*)eptr)[e];
    atomicAdd(&g_deg[r], 1);
}

// Launch 3: fused dinv + exclusive scan (single block, 1024 threads)
__global__ void dinv_scan_kernel() {
    __shared__ int part[1024];
    int t = threadIdx.x;
    const int CH = (NN + 1023) / 1024;  // 98
    int base = t * CH;
    int s = 0;
    for (int i = 0; i < CH; i++) {
        int idx = base + i;
        if (idx < NN) {
            int d = g_deg[idx];
            g_dinv[idx] = rsqrtf((float)d);
            s += d - 1;
        }
    }
    part[t] = s;
    __syncthreads();
    for (int off = 1; off < 1024; off <<= 1) {
        int v = 0;
        if (t >= off) v = part[t - off];
        __syncthreads();
        if (t >= off) part[t] += v;
        __syncthreads();
    }
    int run = (t == 0) ? 0 : part[t - 1];
    for (int i = 0; i < CH; i++) {
        int idx = base + i;
        if (idx < NN) {
            g_rowptr[idx] = run;
            g_cursor[idx] = run;
            run += g_deg[idx] - 1;
        }
    }
    if (t == 1023) g_rowptr[NN] = part[1023];
}

// Launch 4: CSR fill (atomic scatter) + h0/y init fused
// h0 = fp16(x*0.5), y = fp32(x*0.5)
__global__ void fill_init_kernel(const void* __restrict__ eptr,
                                 const float* __restrict__ x) {
    int i = blockIdx.x * blockDim.x + threadIdx.x;
    if (i < NE) {
        int r, c;
        if (g_is64) {
            const long long* q = (const long long*)eptr;
            r = (int)q[i]; c = (int)q[i + NE];
        } else {
            const int* q = (const int*)eptr;
            r = q[i]; c = q[i + NE];
        }
        int pos = atomicAdd(&g_cursor[r], 1);
        EdgeCW ec;
        ec.c = c;
        ec.w = g_dinv[r] * g_dinv[c];
        g_edges[pos] = ec;
    }
    if (i < NN * (NFEAT / 4)) {   // 1.6M float4 units
        float4 v = ((const float4*)x)[i];
        v.x *= 0.5f; v.y *= 0.5f; v.z *= 0.5f; v.w *= 0.5f;
        ((float4*)g_y)[i] = v;
        __half2* h2 = (__half2*)g_h0;
        h2[2 * i]     = __floats2half2_rn(v.x, v.y);
        h2[2 * i + 1] = __floats2half2_rn(v.z, v.w);
    }
}

// ---------------------------------------------------------------------------
// SpMM: one warp per row. Lane-parallel edge fetch (coalesced 32-edge chunk),
// shfl broadcast -> gathers issue back-to-back. fp16 h, fp32 accumulate.
// dst[r] = dinv[r]^2 * src[r] + sum ew*src[col];  y[r] += dst[r]
// ---------------------------------------------------------------------------
__global__ void __launch_bounds__(256) spmm_kernel(int sel) {
    const __half2* __restrict__ src = (const __half2*)(sel ? g_h1 : g_h0);
    __half2*       __restrict__ dst = (__half2*)(sel ? g_h0 : g_h1);
    int gw = (blockIdx.x * blockDim.x + threadIdx.x) >> 5;
    if (gw >= NN) return;
    int lane = threadIdx.x & 31;

    int beg = g_rowptr[gw];
    int end = g_rowptr[gw + 1];
    float di = g_dinv[gw];
    float sw = di * di;

    float2 sv = __half22float2(src[gw * 32 + lane]);
    float2 acc;
    acc.x = sw * sv.x;
    acc.y = sw * sv.y;

    for (int j0 = beg; j0 < end; j0 += 32) {
        int rem = end - j0;
        int n = rem < 32 ? rem : 32;
        int   ec = 0;
        float ew = 0.f;
        if (lane < n) {
            EdgeCW e = g_edges[j0 + lane];
            ec = e.c; ew = e.w;
        }
        for (int k = 0; k < n; k++) {
            int   cc = __shfl_sync(0xffffffffu, ec, k);
            float ww = __shfl_sync(0xffffffffu, ew, k);
            float2 hv = __half22float2(src[cc * 32 + lane]);
            acc.x = fmaf(ww, hv.x, acc.x);
            acc.y = fmaf(ww, hv.y, acc.y);
        }
    }

    dst[gw * 32 + lane] = __floats2half2_rn(acc.x, acc.y);
    float2* y2 = (float2*)g_y;
    float2 yv = y2[gw * 32 + lane];
    yv.x += acc.x;
    yv.y += acc.y;
    y2[gw * 32 + lane] = yv;
}

// ---------------------------------------------------------------------------
// Fused MLP: out = relu((y/9) @ W1 + b1) @ W2 + b2
// 64 rows per block; everything staged in dynamic smem.
// ---------------------------------------------------------------------------
#define MLP_SMEM_FLOATS (64 * 256 + 256 * 40 + 64 * 65 + 64 * 264)

__global__ void __launch_bounds__(256) mlp_kernel(
    const float* __restrict__ W1g, const float* __restrict__ b1g,
    const float* __restrict__ W2g, const float* __restrict__ b2g,
    float* __restrict__ out)
{
    extern __shared__ float sm[];
    float* sW1 = sm;                     // [f][c]  64 x 256 (scaled by 1/9)
    float* sW2 = sW1 + 64 * 256;         // [k][c]  256 x 40
    float* sY  = sW2 + 256 * 40;         // [r][f]  64 x 65 (pad)
    float* sH  = sY  + 64 * 65;          // [r][k]  64 x 264 (pad)

    int t = threadIdx.x;
    int row0 = blockIdx.x * 64;

    for (int i = t; i < 64 * 64; i += 256) {
        int r = i >> 6, f = i & 63;
        float v = (row0 + r < NN) ? g_y[(size_t)(row0 + r) * 64 + f] : 0.f;
        sY[r * 65 + f] = v;
    }
    const float inv9 = 1.0f / 9.0f;
    for (int i = t; i < 64 * 256; i += 256) sW1[i] = W1g[i] * inv9;
    for (int i = t; i < 256 * 40; i += 256) sW2[i] = W2g[i];
    __syncthreads();

    // Phase 1: hid[64][256] = relu(Y @ W1 + b1)
    {
        int rg = t & 7;        // 8 row groups of 8
        int cg = t >> 3;       // 32 col groups of 8
        float acc[8][8];
        #pragma unroll
        for (int i = 0; i < 8; i++)
            #pragma unroll
            for (int j = 0; j < 8; j++) acc[i][j] = 0.f;

        #pragma unroll 4
        for (int f = 0; f < 64; f++) {
            float a[8];
            #pragma unroll
            for (int i = 0; i < 8; i++) a[i] = sY[(8 * rg + i) * 65 + f];
            float4 w0 = *(const float4*)&sW1[f * 256 + 8 * cg];
            float4 w1 = *(const float4*)&sW1[f * 256 + 8 * cg + 4];
            float w[8] = {w0.x, w0.y, w0.z, w0.w, w1.x, w1.y, w1.z, w1.w};
            #pragma unroll
            for (int i = 0; i < 8; i++)
                #pragma unroll
                for (int j = 0; j < 8; j++)
                    acc[i][j] = fmaf(a[i], w[j], acc[i][j]);
        }

        float bv[8];
        #pragma unroll
        for (int j = 0; j < 8; j++) bv[j] = __ldg(&b1g[8 * cg + j]);
        #pragma unroll
        for (int i = 0; i < 8; i++)
            #pragma unroll
            for (int j = 0; j < 8; j++)
                sH[(8 * rg + i) * 264 + 8 * cg + j] = fmaxf(acc[i][j] + bv[j], 0.f);
    }
    __syncthreads();

    // Phase 2: out[64][40] = hid @ W2 + b2
    {
        int r  = t >> 2;       // 64 rows
        int cq = t & 3;        // 4 col groups of 10
        int c0 = cq * 10;
        float acc2[10];
        #pragma unroll
        for (int j = 0; j < 10; j++) acc2[j] = __ldg(&b2g[c0 + j]);

        #pragma unroll 2
        for (int k = 0; k < 256; k++) {
            float hv = sH[r * 264 + k];
            #pragma unroll
            for (int j2 = 0; j2 < 5; j2++) {
                float2 w = *(const float2*)&sW2[k * 40 + c0 + 2 * j2];
                acc2[2 * j2]     = fmaf(hv, w.x, acc2[2 * j2]);
                acc2[2 * j2 + 1] = fmaf(hv, w.y, acc2[2 * j2 + 1]);
            }
        }
        if (row0 + r < NN) {
            #pragma unroll
            for (int j = 0; j < 10; j++)
                out[(size_t)(row0 + r) * 40 + c0 + j] = acc2[j];
        }
    }
}

extern "C" void kernel_launch(void* const* d_in, const int* in_sizes, int n_in,
                              void* d_out, int out_size) {
    const float* x   = (const float*)d_in[0];
    const void*  eix = d_in[1];
    const float* W1  = (const float*)d_in[2];
    const float* b1  = (const float*)d_in[3];
    const float* W2  = (const float*)d_in[4];
    const float* b2  = (const float*)d_in[5];
    float* out = (float*)d_out;

    cudaFuncSetAttribute(mlp_kernel, cudaFuncAttributeMaxDynamicSharedMemorySize,
                         MLP_SMEM_FLOATS * (int)sizeof(float));

    setup1_kernel<<<(NN + 255) / 256, 256>>>((const int*)eix);
    deg_count_kernel<<<(NE + 255) / 256, 256>>>(eix);
    dinv_scan_kernel<<<1, 1024>>>();
    int fi_threads = NN * (NFEAT / 4);  // 1.6M > NE
    fill_init_kernel<<<(fi_threads + 255) / 256, 256>>>(eix, x);

    int spmm_blocks = (NN * 32 + 255) / 256;  // one warp per row
    for (int it = 0; it < 8; it++)
        spmm_kernel<<<spmm_blocks, 256>>>(it & 1);

    int mlp_blocks = (NN + 63) / 64;
    mlp_kernel<<<mlp_blocks, 256, MLP_SMEM_FLOATS * (int)sizeof(float)>>>(
        W1, b1, W2, b2, out);
}